// round 3
// baseline (speedup 1.0000x reference)
#include <cuda_runtime.h>

// ReLU_Conv (CROWN-style ReLU relaxation over bound maps)
// Round 3: 4 neurons per block (MLP=8 front-batched LDG.128/thread),
//          streaming hints, single barrier, simplified reduction masks.
// Output layout: [lx_out | ux_out | lc_out | uc_out]

__device__ __forceinline__ void acc_pair(const float4 l, const float4 u,
                                         const float4 mn, const float4 mx,
                                         float& sl, float& su)
{
    // (l>0 ? mn : (l<0 ? mx : 0)) * l == (l>0 ? mn : mx) * l  (finite bounds)
    sl  = (l.x > 0.f ? mn.x : mx.x) * l.x;
    su  = (u.x > 0.f ? mx.x : mn.x) * u.x;
    sl += (l.y > 0.f ? mn.y : mx.y) * l.y;
    su += (u.y > 0.f ? mx.y : mn.y) * u.y;
    sl += (l.z > 0.f ? mn.z : mx.z) * l.z;
    su += (u.z > 0.f ? mx.z : mn.z) * u.z;
    sl += (l.w > 0.f ? mn.w : mx.w) * l.w;
    su += (u.w > 0.f ? mx.w : mn.w) * u.w;
}

__global__ __launch_bounds__(256, 3)
void relu_conv_kernel(
    const float* __restrict__ lx, const float* __restrict__ ux,
    const float* __restrict__ lc, const float* __restrict__ uc,
    const float* __restrict__ xmin, const float* __restrict__ xmax,
    float* __restrict__ lx_out, float* __restrict__ ux_out,
    float* __restrict__ lc_out, float* __restrict__ uc_out)
{
    const int tid = threadIdx.x;                       // 0..255
    const int n0  = blockIdx.x * 4;                    // neuron quad
    const size_t base = (size_t)n0 * 1024;

    // Front-batched streaming loads: 8x LDG.128 per thread, evict-first.
    const float4* plx = reinterpret_cast<const float4*>(lx + base) + tid;
    const float4* pux = reinterpret_cast<const float4*>(ux + base) + tid;
    float4 vlx[4], vux[4];
    #pragma unroll
    for (int i = 0; i < 4; i++) vlx[i] = __ldcs(plx + i * 256);
    #pragma unroll
    for (int i = 0; i < 4; i++) vux[i] = __ldcs(pux + i * 256);

    // Broadcast bounds: reused by every block -> normal caching.
    const float4 vmn = __ldg(reinterpret_cast<const float4*>(xmin) + tid);
    const float4 vmx = __ldg(reinterpret_cast<const float4*>(xmax) + tid);

    float sl[4], su[4];
    #pragma unroll
    for (int i = 0; i < 4; i++)
        acc_pair(vlx[i], vux[i], vmn, vmx, sl[i], su[i]);

    // Warp reduction of 8 partials.
    #pragma unroll
    for (int off = 16; off; off >>= 1) {
        #pragma unroll
        for (int i = 0; i < 4; i++) {
            sl[i] += __shfl_down_sync(0xffffffffu, sl[i], off);
            su[i] += __shfl_down_sync(0xffffffffu, su[i], off);
        }
    }

    __shared__ float4 sL[8], sU[8];                    // per-warp partials
    const int warp = tid >> 5, lane = tid & 31;
    if (lane == 0) {
        sL[warp] = make_float4(sl[0], sl[1], sl[2], sl[3]);
        sU[warp] = make_float4(su[0], su[1], su[2], su[3]);
    }
    __syncthreads();                                   // the ONLY barrier

    // Every thread redundantly finalizes (broadcast smem reads).
    float l[4] = {0.f, 0.f, 0.f, 0.f}, u[4] = {0.f, 0.f, 0.f, 0.f};
    #pragma unroll
    for (int i = 0; i < 8; i++) {
        const float4 pL = sL[i], pU = sU[i];
        l[0] += pL.x; l[1] += pL.y; l[2] += pL.z; l[3] += pL.w;
        u[0] += pU.x; u[1] += pU.y; u[2] += pU.z; u[3] += pU.w;
    }

    bool alive[4], cross[4];
    float slope[4];
    #pragma unroll
    for (int i = 0; i < 4; i++) {
        const float lcv = lc[n0 + i], ucv = uc[n0 + i];
        l[i] += lcv; u[i] += ucv;
        alive[i] = (l[i] >= 0.f);
        cross[i] = (l[i] < 0.f) && (u[i] > 0.f);
        float s = cross[i] ? (u[i] / (u[i] - l[i])) : 1.f;
        slope[i] = fminf(fmaxf(s, 0.f), 1.f);
        if (tid == 0) {
            lc_out[n0 + i] = alive[i] ? lcv : 0.f;
            uc_out[n0 + i] = alive[i] ? ucv
                           : (cross[i] ? (slope[i] * ucv - slope[i] * l[i]) : 0.f);
        }
    }

    float4* qlx = reinterpret_cast<float4*>(lx_out + base) + tid;
    float4* qux = reinterpret_cast<float4*>(ux_out + base) + tid;
    #pragma unroll
    for (int i = 0; i < 4; i++) {
        float4 o;
        o.x = alive[i] ? vlx[i].x : 0.f;
        o.y = alive[i] ? vlx[i].y : 0.f;
        o.z = alive[i] ? vlx[i].z : 0.f;
        o.w = alive[i] ? vlx[i].w : 0.f;
        __stcs(qlx + i * 256, o);
    }
    #pragma unroll
    for (int i = 0; i < 4; i++) {
        float4 o;
        o.x = alive[i] ? vux[i].x : (cross[i] ? slope[i] * vux[i].x : 0.f);
        o.y = alive[i] ? vux[i].y : (cross[i] ? slope[i] * vux[i].y : 0.f);
        o.z = alive[i] ? vux[i].z : (cross[i] ? slope[i] * vux[i].z : 0.f);
        o.w = alive[i] ? vux[i].w : (cross[i] ? slope[i] * vux[i].w : 0.f);
        __stcs(qux + i * 256, o);
    }
}

extern "C" void kernel_launch(void* const* d_in, const int* in_sizes, int n_in,
                              void* d_out, int out_size)
{
    const float* lx   = (const float*)d_in[0];
    const float* ux   = (const float*)d_in[1];
    const float* lc   = (const float*)d_in[2];
    const float* uc   = (const float*)d_in[3];
    const float* xmin = (const float*)d_in[4];
    const float* xmax = (const float*)d_in[5];

    const int neurons = in_sizes[2];          // C*H*W = 32768
    const size_t nel  = (size_t)neurons * 1024;

    float* out    = (float*)d_out;
    float* lx_out = out;
    float* ux_out = out + nel;
    float* lc_out = out + 2 * nel;
    float* uc_out = out + 2 * nel + neurons;

    relu_conv_kernel<<<neurons / 4, 256>>>(lx, ux, lc, uc, xmin, xmax,
                                           lx_out, ux_out, lc_out, uc_out);
}